// round 1
// baseline (speedup 1.0000x reference)
#include <cuda_runtime.h>

#define BATCH 1024
#define SEQT  256
#define DIN   128
#define HID   512
#define ZD    64
#define G4    2048   // 4*HID
#define KTOT  640    // DIN + HID

// Persistent state (static device globals — allocation-free per harness rules)
__device__ float g_h[2][BATCH * HID];   // ping-pong hidden state
__device__ float g_c[BATCH * HID];      // cell state

__device__ __forceinline__ float sigmoidf_(float v) {
    return 1.0f / (1.0f + __expf(-v));
}
__device__ __forceinline__ float softplusf_(float v) {
    return (v > 20.0f) ? v : log1pf(__expf(v));
}

// Tiling
constexpr int BM = 128;   // batch rows per block
constexpr int BH = 32;    // hidden units per block (x4 gates -> 128 output cols)
constexpr int BN = 128;   // 4 * BH
constexpr int KT = 16;    // K tile
constexpr int LDA = BM + 4;
constexpr int LDB = BN + 4;

// grid: (HID/BH = 16, BATCH/BM = 8), block: 256 threads
__global__ __launch_bounds__(256) void lstm_step_kernel(
    const float* __restrict__ x,
    const float* __restrict__ W,
    const float* __restrict__ U,
    const float* __restrict__ bias,
    int t)
{
    __shared__ float As[KT][LDA];
    __shared__ float Bs[KT][LDB];

    const float* __restrict__ hin  = g_h[t & 1];
    float* __restrict__       hout = g_h[(t + 1) & 1];

    const int hh0 = blockIdx.x * BH;
    const int bm0 = blockIdx.y * BM;
    const int tid = threadIdx.x;
    const int tcol = tid & 15;   // 16 thread-cols, each owns 2 hidden units
    const int trow = tid >> 4;   // 16 thread-rows, each owns 8 batch rows

    float acc[8][2][4];          // [row][hidden-unit][gate]
#pragma unroll
    for (int i = 0; i < 8; i++)
#pragma unroll
        for (int u = 0; u < 2; u++)
#pragma unroll
            for (int g = 0; g < 4; g++)
                acc[i][u][g] = 0.0f;

    for (int kt = 0; kt < KTOT; kt += KT) {
        // ---- load A tile: [BM rows][KT k] as 512 float4 (along k), transposed into smem
#pragma unroll
        for (int p = 0; p < 2; p++) {
            int idx = p * 256 + tid;
            int kq  = idx & 3;       // which float4 along k
            int row = idx >> 2;      // 0..127
            int kl  = kq * 4;
            const float* src;
            if (kt < DIN)
                src = x + (size_t)(bm0 + row) * (SEQT * DIN) + (size_t)t * DIN + kt + kl;
            else
                src = hin + (size_t)(bm0 + row) * HID + (kt - DIN) + kl;
            float4 v = *reinterpret_cast<const float4*>(src);
            As[kl + 0][row] = v.x;
            As[kl + 1][row] = v.y;
            As[kl + 2][row] = v.z;
            As[kl + 3][row] = v.w;
        }
        // ---- load B tile: [KT k][BN cols], cols = gate-major {g*HID + hh0 + j}
#pragma unroll
        for (int p = 0; p < 2; p++) {
            int idx = p * 256 + tid;
            int n4  = idx & 31;      // 32 float4 across 128 cols
            int k   = idx >> 5;      // 0..15
            int n   = n4 * 4;
            int g   = n >> 5;        // gate index 0..3
            int j   = n & 31;        // hidden offset within tile
            int col = g * HID + hh0 + j;
            int kg  = kt + k;
            const float* src = (kg < DIN)
                ? (W + (size_t)kg * G4 + col)
                : (U + (size_t)(kg - DIN) * G4 + col);
            float4 v = *reinterpret_cast<const float4*>(src);
            *reinterpret_cast<float4*>(&Bs[k][n]) = v;
        }
        __syncthreads();

#pragma unroll
        for (int kk = 0; kk < KT; kk++) {
            float a[8];
            float4 a0 = *reinterpret_cast<const float4*>(&As[kk][trow * 8]);
            float4 a1 = *reinterpret_cast<const float4*>(&As[kk][trow * 8 + 4]);
            a[0] = a0.x; a[1] = a0.y; a[2] = a0.z; a[3] = a0.w;
            a[4] = a1.x; a[5] = a1.y; a[6] = a1.z; a[7] = a1.w;

            float bf[2][4];
#pragma unroll
            for (int g = 0; g < 4; g++) {
                float2 bv = *reinterpret_cast<const float2*>(&Bs[kk][g * BH + tcol * 2]);
                bf[0][g] = bv.x;
                bf[1][g] = bv.y;
            }
#pragma unroll
            for (int i = 0; i < 8; i++)
#pragma unroll
                for (int u = 0; u < 2; u++)
#pragma unroll
                    for (int g = 0; g < 4; g++)
                        acc[i][u][g] = fmaf(a[i], bf[u][g], acc[i][u][g]);
        }
        __syncthreads();
    }

    // ---- LSTM pointwise epilogue (all 4 gates are register-local per thread)
#pragma unroll
    for (int i = 0; i < 8; i++) {
        int bi = bm0 + trow * 8 + i;
#pragma unroll
        for (int u = 0; u < 2; u++) {
            int hh = hh0 + tcol * 2 + u;
            float gi = acc[i][u][0] + bias[hh];
            float gf = acc[i][u][1] + bias[HID + hh];
            float gg = acc[i][u][2] + bias[2 * HID + hh];
            float go = acc[i][u][3] + bias[3 * HID + hh];
            float iv = sigmoidf_(gi);
            float fv = sigmoidf_(gf);
            float gv = softplusf_(gg);
            float ov = sigmoidf_(go);
            size_t off = (size_t)bi * HID + hh;
            float cn = fv * g_c[off] + iv * gv;
            g_c[off]  = cn;
            hout[off] = ov * softplusf_(cn);
        }
    }
}

__global__ void zero_state_kernel() {
    int i = blockIdx.x * blockDim.x + threadIdx.x;
    if (i < BATCH * HID) {
        g_h[0][i] = 0.0f;
        g_c[i]    = 0.0f;
    }
}

// grid: BATCH blocks, ZD threads. Final h lives in g_h[0] (t=255 writes buf (255+1)&1 = 0).
__global__ void vae_head_kernel(
    const float* __restrict__ eps,
    const float* __restrict__ Wm, const float* __restrict__ bm,
    const float* __restrict__ Wv, const float* __restrict__ bv,
    float* __restrict__ out)
{
    int b = blockIdx.x;
    int z = threadIdx.x;
    const float* __restrict__ h = g_h[0] + (size_t)b * HID;
    float am = 0.0f, av = 0.0f;
#pragma unroll 8
    for (int k = 0; k < HID; k++) {
        float hv = h[k];
        am = fmaf(hv, Wm[(size_t)k * ZD + z], am);
        av = fmaf(hv, Wv[(size_t)k * ZD + z], av);
    }
    float mu = am + bm[z];
    float lv = av + bv[z];
    size_t o = (size_t)b * ZD + z;
    out[o]                    = mu;                               // mu
    out[(size_t)BATCH * ZD + o]   = lv;                           // logvar
    out[2 * (size_t)BATCH * ZD + o] = mu + eps[o] * __expf(0.5f * lv);  // z
}

extern "C" void kernel_launch(void* const* d_in, const int* in_sizes, int n_in,
                              void* d_out, int out_size)
{
    const float* x    = (const float*)d_in[0];
    const float* eps  = (const float*)d_in[1];
    const float* W    = (const float*)d_in[2];
    const float* U    = (const float*)d_in[3];
    const float* bias = (const float*)d_in[4];
    const float* Wm   = (const float*)d_in[5];
    const float* bm   = (const float*)d_in[6];
    const float* Wv   = (const float*)d_in[7];
    const float* bv   = (const float*)d_in[8];
    float* out = (float*)d_out;

    zero_state_kernel<<<(BATCH * HID + 255) / 256, 256>>>();

    dim3 grid(HID / BH, BATCH / BM);   // (16, 8)
    for (int t = 0; t < SEQT; t++) {
        lstm_step_kernel<<<grid, 256>>>(x, W, U, bias, t);
    }

    vae_head_kernel<<<BATCH, ZD>>>(eps, Wm, bm, Wv, bv, out);
}

// round 2
// speedup vs baseline: 1.9236x; 1.9236x over previous
#include <cuda_runtime.h>
#include <cstdint>

#define BATCH 1024
#define SEQT  256
#define DIN   128
#define HID   512
#define ZD    64
#define G4    2048   // 4*HID
#define KTOT  640    // DIN + HID

__device__ float g_h[2][BATCH * HID];   // ping-pong hidden state (fp32)
__device__ float g_c[BATCH * HID];      // cell state

__device__ __forceinline__ float sigmoidf_(float v) {
    return 1.0f / (1.0f + __expf(-v));
}
__device__ __forceinline__ float softplusf_(float v) {
    return (v > 20.0f) ? v : log1pf(__expf(v));
}
__device__ __forceinline__ uint32_t f2tf32(float f) {
    uint32_t r;
    asm("cvt.rna.tf32.f32 %0, %1;" : "=r"(r) : "f"(f));
    return r;
}
__device__ __forceinline__ void mma_tf32(float c[4], const uint32_t a[4], const uint32_t b[2]) {
    asm volatile(
        "mma.sync.aligned.m16n8k8.row.col.f32.tf32.tf32.f32 "
        "{%0,%1,%2,%3}, {%4,%5,%6,%7}, {%8,%9}, {%0,%1,%2,%3};"
        : "+f"(c[0]), "+f"(c[1]), "+f"(c[2]), "+f"(c[3])
        : "r"(a[0]), "r"(a[1]), "r"(a[2]), "r"(a[3]), "r"(b[0]), "r"(b[1]));
}

// Tiling: block = 64(M) x 128(N local: 32 hidden units x 4 gates), KT=16
constexpr int BM  = 64;
constexpr int BHU = 32;    // hidden units per block
constexpr int KT  = 16;
constexpr int LDA = 72;    // 64 + 8  (bank: 8*k + m distinct)
constexpr int LDB = 136;   // 128 + 8 (bank: 8*k + n distinct)
constexpr int NSTAGES = KTOT / KT;   // 40

// Local column layout in Bs: n = grp*32 + g*8 + j  (grp = warp n-group, g = gate, j = hidden-in-8)
// Actual weight column: g*HID + hh0 + grp*8 + j

// grid: (HID/BHU = 16, BATCH/BM = 16), block: 256 threads (8 warps: 2 M x 4 N-groups)
__global__ __launch_bounds__(256) void lstm_step_kernel(
    const float* __restrict__ x,
    const float* __restrict__ W,
    const float* __restrict__ U,
    const float* __restrict__ bias,
    int t)
{
    __shared__ uint32_t As[2][KT][LDA];
    __shared__ uint32_t Bs[2][KT][LDB];

    const float* __restrict__ hin  = g_h[t & 1];
    float* __restrict__       hout = g_h[(t + 1) & 1];

    const int hh0 = blockIdx.x * BHU;
    const int bm0 = blockIdx.y * BM;
    const int tid = threadIdx.x;
    const int warp = tid >> 5;
    const int lane = tid & 31;
    const int wm = warp & 1;      // M half (32 rows)
    const int wn = warp >> 1;     // N group (8 hidden units x 4 gates)
    const int qid = lane >> 2;    // 0..7
    const int qtr = lane & 3;     // 0..3

    // ---- global load mappings
    // A: 64 rows x 16 k = 256 float4 (along k). row = tid>>2, kq = tid&3.
    const int a_row = tid >> 2;
    const int a_kq  = tid & 3;
    // B: 16 k x 128 n = 512 float4 (along n), two parts p=0,1.
    int b_k[2], b_col[2];
#pragma unroll
    for (int p = 0; p < 2; p++) {
        int idx = p * 256 + tid;
        int n4  = idx & 31;
        b_k[p]  = idx >> 5;            // 0..15
        int n   = n4 * 4;
        int j0  = n & 7;               // 0 or 4
        int g   = (n >> 3) & 3;
        int grp = n >> 5;
        b_col[p] = g * HID + hh0 + grp * 8 + j0;
    }

    float acc[2][4][4];   // [m_tile][gate][c0..c3]
#pragma unroll
    for (int mt = 0; mt < 2; mt++)
#pragma unroll
        for (int g = 0; g < 4; g++)
#pragma unroll
            for (int q = 0; q < 4; q++)
                acc[mt][g][q] = 0.0f;

    // ---- prologue: load stage 0 into buf 0
    {
        const int kb = 0;
        const float* asrc = x + (size_t)(bm0 + a_row) * (SEQT * DIN) + (size_t)t * DIN + kb + a_kq * 4;
        float4 av = *reinterpret_cast<const float4*>(asrc);
        As[0][a_kq * 4 + 0][a_row] = f2tf32(av.x);
        As[0][a_kq * 4 + 1][a_row] = f2tf32(av.y);
        As[0][a_kq * 4 + 2][a_row] = f2tf32(av.z);
        As[0][a_kq * 4 + 3][a_row] = f2tf32(av.w);
#pragma unroll
        for (int p = 0; p < 2; p++) {
            const float* bsrc = W + (size_t)(kb + b_k[p]) * G4 + b_col[p];
            float4 bv = *reinterpret_cast<const float4*>(bsrc);
            uint4 u;
            u.x = f2tf32(bv.x); u.y = f2tf32(bv.y); u.z = f2tf32(bv.z); u.w = f2tf32(bv.w);
            int idx = p * 256 + tid;
            int n   = (idx & 31) * 4;
            *reinterpret_cast<uint4*>(&Bs[0][b_k[p]][n]) = u;
        }
    }
    __syncthreads();

    int cur = 0;
    for (int s = 0; s < NSTAGES; s++) {
        // ---- prefetch stage s+1 into registers
        float4 av;
        float4 bv[2];
        const bool has_next = (s + 1 < NSTAGES);
        if (has_next) {
            const int kb = (s + 1) * KT;
            const float* asrc = (kb < DIN)
                ? x   + (size_t)(bm0 + a_row) * (SEQT * DIN) + (size_t)t * DIN + kb + a_kq * 4
                : hin + (size_t)(bm0 + a_row) * HID + (kb - DIN) + a_kq * 4;
            av = *reinterpret_cast<const float4*>(asrc);
#pragma unroll
            for (int p = 0; p < 2; p++) {
                int kg = kb + b_k[p];
                const float* bsrc = (kg < DIN)
                    ? W + (size_t)kg * G4 + b_col[p]
                    : U + (size_t)(kg - DIN) * G4 + b_col[p];
                bv[p] = *reinterpret_cast<const float4*>(bsrc);
            }
        }

        // ---- compute on buf[cur]
#pragma unroll
        for (int kk = 0; kk < KT; kk += 8) {
            uint32_t af[2][4];
#pragma unroll
            for (int mt = 0; mt < 2; mt++) {
                int m = wm * 32 + mt * 16 + qid;
                af[mt][0] = As[cur][kk + qtr][m];
                af[mt][1] = As[cur][kk + qtr][m + 8];
                af[mt][2] = As[cur][kk + 4 + qtr][m];
                af[mt][3] = As[cur][kk + 4 + qtr][m + 8];
            }
            uint32_t bf[4][2];
#pragma unroll
            for (int g = 0; g < 4; g++) {
                int n = wn * 32 + g * 8 + qid;
                bf[g][0] = Bs[cur][kk + qtr][n];
                bf[g][1] = Bs[cur][kk + 4 + qtr][n];
            }
#pragma unroll
            for (int mt = 0; mt < 2; mt++)
#pragma unroll
                for (int g = 0; g < 4; g++)
                    mma_tf32(acc[mt][g], af[mt], bf[g]);
        }

        // ---- store prefetched stage into the other buffer
        if (has_next) {
            int nxt = cur ^ 1;
            As[nxt][a_kq * 4 + 0][a_row] = f2tf32(av.x);
            As[nxt][a_kq * 4 + 1][a_row] = f2tf32(av.y);
            As[nxt][a_kq * 4 + 2][a_row] = f2tf32(av.z);
            As[nxt][a_kq * 4 + 3][a_row] = f2tf32(av.w);
#pragma unroll
            for (int p = 0; p < 2; p++) {
                uint4 u;
                u.x = f2tf32(bv[p].x); u.y = f2tf32(bv[p].y);
                u.z = f2tf32(bv[p].z); u.w = f2tf32(bv[p].w);
                int idx = p * 256 + tid;
                int n   = (idx & 31) * 4;
                *reinterpret_cast<uint4*>(&Bs[nxt][b_k[p]][n]) = u;
            }
        }
        __syncthreads();
        cur ^= 1;
    }

    // ---- LSTM pointwise epilogue (gates are register-local: acc[mt][gate][...])
#pragma unroll
    for (int mt = 0; mt < 2; mt++) {
#pragma unroll
        for (int half = 0; half < 2; half++) {
            int row = bm0 + wm * 32 + mt * 16 + qid + half * 8;
#pragma unroll
            for (int u = 0; u < 2; u++) {
                int hh = hh0 + wn * 8 + qtr * 2 + u;
                int q  = half * 2 + u;
                float gi = acc[mt][0][q] + bias[hh];
                float gf = acc[mt][1][q] + bias[HID + hh];
                float gg = acc[mt][2][q] + bias[2 * HID + hh];
                float go = acc[mt][3][q] + bias[3 * HID + hh];
                float iv = sigmoidf_(gi);
                float fv = sigmoidf_(gf);
                float gv = softplusf_(gg);
                float ov = sigmoidf_(go);
                size_t off = (size_t)row * HID + hh;
                float cn = fv * g_c[off] + iv * gv;
                g_c[off]  = cn;
                hout[off] = ov * softplusf_(cn);
            }
        }
    }
}

__global__ void zero_state_kernel() {
    int i = blockIdx.x * blockDim.x + threadIdx.x;
    if (i < BATCH * HID) {
        g_h[0][i] = 0.0f;
        g_c[i]    = 0.0f;
    }
}

// Final h is in g_h[0] (t=255 writes buf (255+1)&1 = 0). Head stays pure fp32.
__global__ void vae_head_kernel(
    const float* __restrict__ eps,
    const float* __restrict__ Wm, const float* __restrict__ bm,
    const float* __restrict__ Wv, const float* __restrict__ bv,
    float* __restrict__ out)
{
    int b = blockIdx.x;
    int z = threadIdx.x;
    const float* __restrict__ h = g_h[0] + (size_t)b * HID;
    float am = 0.0f, av = 0.0f;
#pragma unroll 8
    for (int k = 0; k < HID; k++) {
        float hv = h[k];
        am = fmaf(hv, Wm[(size_t)k * ZD + z], am);
        av = fmaf(hv, Wv[(size_t)k * ZD + z], av);
    }
    float mu = am + bm[z];
    float lv = av + bv[z];
    size_t o = (size_t)b * ZD + z;
    out[o]                          = mu;
    out[(size_t)BATCH * ZD + o]     = lv;
    out[2 * (size_t)BATCH * ZD + o] = mu + eps[o] * __expf(0.5f * lv);
}

extern "C" void kernel_launch(void* const* d_in, const int* in_sizes, int n_in,
                              void* d_out, int out_size)
{
    const float* x    = (const float*)d_in[0];
    const float* eps  = (const float*)d_in[1];
    const float* W    = (const float*)d_in[2];
    const float* U    = (const float*)d_in[3];
    const float* bias = (const float*)d_in[4];
    const float* Wm   = (const float*)d_in[5];
    const float* bm   = (const float*)d_in[6];
    const float* Wv   = (const float*)d_in[7];
    const float* bv   = (const float*)d_in[8];
    float* out = (float*)d_out;

    zero_state_kernel<<<(BATCH * HID + 255) / 256, 256>>>();

    dim3 grid(HID / BHU, BATCH / BM);   // (16, 16) = 256 blocks
    for (int t = 0; t < SEQT; t++) {
        lstm_step_kernel<<<grid, 256>>>(x, W, U, bias, t);
    }

    vae_head_kernel<<<BATCH, ZD>>>(eps, Wm, bm, Wv, bv, out);
}